// round 1
// baseline (speedup 1.0000x reference)
#include <cuda_runtime.h>
#include <cstdint>

// Problem constants
#define NSEQ    512
#define EMB     128
#define NHEADS  8
#define HDIM    16
#define NBATCH  512          // B*H*C = 32*8*2
#define M_TOTAL 32768        // B*C*N = 32*2*512

// Scratch (allocation-free rule: __device__ globals)
__device__ float g_qs[NBATCH * NSEQ * HDIM];   // [g=b*16+h*2+c][n][d]
__device__ float g_ks[NBATCH * NSEQ * HDIM];
__device__ float g_vs[NBATCH * NSEQ * HDIM];
__device__ float g_att[(size_t)M_TOTAL * EMB]; // [(b*2+c)*512+n][h*16+d]

// ---------------------------------------------------------------------------
// GEMM: out = X @ W^T      X: [M,128] row-major, W: [128,128] (torch Linear)
// headsplit=1: write out in [b,h,c,n,d] layout (projections)
// headsplit=0: plain [m,f] layout (final output projection)
// Block: 256 threads, tile = 64 rows x 128 cols, thread tile 4x8.
// Smem: Wt[e][f] (64KB, transposed for vector loads) + xs[64][128] (32KB).
// ---------------------------------------------------------------------------
__global__ __launch_bounds__(256) void gemm128(const float* __restrict__ X,
                                               const float* __restrict__ W,
                                               float* __restrict__ out,
                                               int headsplit) {
    extern __shared__ float sm[];
    float* Wt = sm;             // 128*128 : Wt[e*128 + f] = W[f*128 + e]
    float* xs = sm + 16384;     // 64*128  : xs[r*128 + e]
    const int tid  = threadIdx.x;
    const int row0 = blockIdx.x * 64;

    for (int idx = tid; idx < 16384; idx += 256) {
        int f = idx >> 7, e = idx & 127;
        Wt[(e << 7) + f] = W[idx];
    }
    {
        const float4* Xv  = (const float4*)(X + (size_t)row0 * EMB);
        float4*       xsv = (float4*)xs;
        for (int idx = tid; idx < 2048; idx += 256) xsv[idx] = Xv[idx];
    }
    __syncthreads();

    const int rg = tid >> 4;          // row group  0..15 (4 rows each)
    const int f0 = (tid & 15) << 3;   // col start  0..120 step 8

    float acc[4][8];
#pragma unroll
    for (int r = 0; r < 4; r++)
#pragma unroll
        for (int j = 0; j < 8; j++) acc[r][j] = 0.f;

    const float* x0 = xs + (rg * 4) * EMB;

#pragma unroll 2
    for (int e = 0; e < 128; e++) {
        float4 wa = *(const float4*)(Wt + (e << 7) + f0);
        float4 wb = *(const float4*)(Wt + (e << 7) + f0 + 4);
        float xv[4];
#pragma unroll
        for (int r = 0; r < 4; r++) xv[r] = x0[r * EMB + e];
#pragma unroll
        for (int r = 0; r < 4; r++) {
            acc[r][0] += xv[r] * wa.x;
            acc[r][1] += xv[r] * wa.y;
            acc[r][2] += xv[r] * wa.z;
            acc[r][3] += xv[r] * wa.w;
            acc[r][4] += xv[r] * wb.x;
            acc[r][5] += xv[r] * wb.y;
            acc[r][6] += xv[r] * wb.z;
            acc[r][7] += xv[r] * wb.w;
        }
    }

#pragma unroll
    for (int r = 0; r < 4; r++) {
        const int m = row0 + rg * 4 + r;
        float4 va = make_float4(acc[r][0], acc[r][1], acc[r][2], acc[r][3]);
        float4 vb = make_float4(acc[r][4], acc[r][5], acc[r][6], acc[r][7]);
        if (headsplit) {
            // m = (b*2+c)*512 + n ; f = h*16 + dd (8 consecutive f share h)
            int b = m >> 10, c = (m >> 9) & 1, n = m & 511;
            int h = f0 >> 4, dd = f0 & 15;
            size_t o = ((size_t)((b * 16 + h * 2 + c) * NSEQ + n)) * HDIM + dd;
            *(float4*)(out + o)     = va;
            *(float4*)(out + o + 4) = vb;
        } else {
            size_t o = (size_t)m * EMB + f0;
            *(float4*)(out + o)     = va;
            *(float4*)(out + o + 4) = vb;
        }
    }
}

// ---------------------------------------------------------------------------
// Attention for one (b,h,c) batch. K,V tiles resident in smem (64KB) + mask.
// 256 threads, 2 queries per thread. Single pass, no max tracking:
//   logit L = 10*tanh(dot/4) <= 10  =>  fixed max = 10
//   p = exp(L - 10) = exp(-20 / (exp(dot/2) + 1))   (exact identity)
//   masked key: p = 0.    out = (sum p*v) / (sum p)
// ---------------------------------------------------------------------------
__global__ __launch_bounds__(256) void attn(const float* __restrict__ mask) {
    extern __shared__ float sm[];
    float* ksm = sm;            // 512*16
    float* vsm = sm + 8192;     // 512*16
    float* msm = sm + 16384;    // 512 multipliers (0 = masked, 1 = keep)
    const int g   = blockIdx.x;
    const int tid = threadIdx.x;
    const int b = g >> 4, h = (g >> 1) & 7, c = g & 1;

    {
        const float4* kg  = (const float4*)(g_ks + (size_t)g * (NSEQ * HDIM));
        const float4* vg  = (const float4*)(g_vs + (size_t)g * (NSEQ * HDIM));
        float4* ksv = (float4*)ksm;
        float4* vsv = (float4*)vsm;
        for (int idx = tid; idx < 2048; idx += 256) {
            ksv[idx] = kg[idx];
            vsv[idx] = vg[idx];
        }
        // mask words: nonzero => masked (works for float32 1.0/0.0 and int32 1/0)
        const unsigned* mrow = (const unsigned*)mask + (b * 2 + c) * NSEQ;
        for (int idx = tid; idx < NSEQ; idx += 256)
            msm[idx] = (mrow[idx] != 0u) ? 0.f : 1.f;
    }
    __syncthreads();

    float q0[16], q1[16], a0[16], a1[16];
    {
        const float* qg = g_qs + (size_t)g * (NSEQ * HDIM);
#pragma unroll
        for (int d4 = 0; d4 < 4; d4++) {
            *(float4*)(q0 + 4 * d4) = *(const float4*)(qg + (size_t)tid * HDIM + 4 * d4);
            *(float4*)(q1 + 4 * d4) = *(const float4*)(qg + (size_t)(tid + 256) * HDIM + 4 * d4);
        }
#pragma unroll
        for (int d = 0; d < 16; d++) { a0[d] = 0.f; a1[d] = 0.f; }
    }
    float l0 = 0.f, l1 = 0.f;

    for (int j = 0; j < NSEQ; j++) {
        float kj[16], vj[16];
#pragma unroll
        for (int d4 = 0; d4 < 4; d4++) {
            *(float4*)(kj + 4 * d4) = *(const float4*)(ksm + j * HDIM + 4 * d4);
            *(float4*)(vj + 4 * d4) = *(const float4*)(vsm + j * HDIM + 4 * d4);
        }
        float s0a = 0.f, s0b = 0.f, s1a = 0.f, s1b = 0.f;
#pragma unroll
        for (int d = 0; d < 16; d += 2) {
            s0a += q0[d]     * kj[d];
            s0b += q0[d + 1] * kj[d + 1];
            s1a += q1[d]     * kj[d];
            s1b += q1[d + 1] * kj[d + 1];
        }
        const float s0 = s0a + s0b;
        const float s1 = s1a + s1b;
        const float mj = msm[j];
        // p = exp(-20/(exp(dot/2)+1));  exp(dot/2)=inf handled (rcp->0 => p=1)
        float t0 = __expf(s0 * 0.5f);
        float t1 = __expf(s1 * 0.5f);
        float p0 = __expf(__fdividef(-20.f, t0 + 1.f)) * mj;
        float p1 = __expf(__fdividef(-20.f, t1 + 1.f)) * mj;
        l0 += p0;
        l1 += p1;
#pragma unroll
        for (int d = 0; d < 16; d++) {
            a0[d] += p0 * vj[d];
            a1[d] += p1 * vj[d];
        }
    }

    const float inv0 = 1.f / l0;
    const float inv1 = 1.f / l1;
    const int mbase = (b * 2 + c) * NSEQ;
    float* o0 = g_att + (size_t)(mbase + tid) * EMB + h * HDIM;
    float* o1 = g_att + (size_t)(mbase + tid + 256) * EMB + h * HDIM;
#pragma unroll
    for (int d4 = 0; d4 < 4; d4++) {
        *(float4*)(o0 + 4 * d4) = make_float4(a0[4 * d4] * inv0, a0[4 * d4 + 1] * inv0,
                                              a0[4 * d4 + 2] * inv0, a0[4 * d4 + 3] * inv0);
        *(float4*)(o1 + 4 * d4) = make_float4(a1[4 * d4] * inv1, a1[4 * d4 + 1] * inv1,
                                              a1[4 * d4 + 2] * inv1, a1[4 * d4 + 3] * inv1);
    }
}

// ---------------------------------------------------------------------------
extern "C" void kernel_launch(void* const* d_in, const int* in_sizes, int n_in,
                              void* d_out, int out_size) {
    const float* Q    = (const float*)d_in[0];
    const float* K    = (const float*)d_in[1];
    const float* V    = (const float*)d_in[2];
    const float* mask = (const float*)d_in[3];
    const float* Wq   = (const float*)d_in[4];
    const float* Wk   = (const float*)d_in[5];
    const float* Wv   = (const float*)d_in[6];
    const float* Wout = (const float*)d_in[7];
    float* out = (float*)d_out;

    const int GEMM_SMEM = (16384 + 8192) * 4;        // 96 KB
    const int ATTN_SMEM = (8192 + 8192 + 512) * 4;   // 66 KB
    cudaFuncSetAttribute(gemm128, cudaFuncAttributeMaxDynamicSharedMemorySize, GEMM_SMEM);
    cudaFuncSetAttribute(attn,    cudaFuncAttributeMaxDynamicSharedMemorySize, ATTN_SMEM);

    float *qs, *ks, *vs, *att;
    cudaGetSymbolAddress((void**)&qs,  g_qs);
    cudaGetSymbolAddress((void**)&ks,  g_ks);
    cudaGetSymbolAddress((void**)&vs,  g_vs);
    cudaGetSymbolAddress((void**)&att, g_att);

    gemm128<<<M_TOTAL / 64, 256, GEMM_SMEM>>>(Q, Wq, qs, 1);
    gemm128<<<M_TOTAL / 64, 256, GEMM_SMEM>>>(K, Wk, ks, 1);
    gemm128<<<M_TOTAL / 64, 256, GEMM_SMEM>>>(V, Wv, vs, 1);
    attn<<<NBATCH, 256, ATTN_SMEM>>>(mask);
    gemm128<<<M_TOTAL / 64, 256, GEMM_SMEM>>>(att, Wout, out, 0);
}

// round 7
// speedup vs baseline: 1.7090x; 1.7090x over previous
#include <cuda_runtime.h>
#include <cuda_bf16.h>
#include <cstdint>

#define NSEQ    512
#define EMB     128
#define HDIM    16
#define NBATCH  512          // B*H*C
#define M_TOTAL 32768        // B*C*N

// Scratch (__device__ globals per allocation rules)
__device__ float g_qs[NBATCH * NSEQ * HDIM];
__device__ float g_ks[NBATCH * NSEQ * HDIM];
__device__ float g_vs[NBATCH * NSEQ * HDIM];
__device__ float g_att[(size_t)M_TOTAL * EMB];

// ---------------------------------------------------------------------------
// mma.sync m16n8k16 bf16 (arch-unconditional HMMA; works on base sm_103)
// D = A(16x16 row) * B(16x8 col) + D, fp32 accum.
// Fragment coords (lane = 4*gid + tig):
//   A: a0=(gid,2tig..+1) a1=(gid+8,2tig..+1) a2=(gid,2tig+8..+9) a3=(gid+8,2tig+8..+9)
//   B: b0=(k=2tig..+1, n=gid) b1=(k=2tig+8..+9, n=gid)
//   C: c0=(gid,2tig) c1=(gid,2tig+1) c2=(gid+8,2tig) c3=(gid+8,2tig+1)
// ---------------------------------------------------------------------------
__device__ __forceinline__ void mma16816(float* c, const uint32_t* a, const uint32_t* b) {
    asm volatile(
        "mma.sync.aligned.m16n8k16.row.col.f32.bf16.bf16.f32 "
        "{%0,%1,%2,%3}, {%4,%5,%6,%7}, {%8,%9}, {%0,%1,%2,%3};"
        : "+f"(c[0]), "+f"(c[1]), "+f"(c[2]), "+f"(c[3])
        : "r"(a[0]), "r"(a[1]), "r"(a[2]), "r"(a[3]), "r"(b[0]), "r"(b[1]));
}

// Split fp32 -> bf16 hi + lo (x ~= hi + lo, err ~2^-17 rel)
__device__ __forceinline__ void split4(__nv_bfloat16* ph, __nv_bfloat16* pl, float4 v) {
    __nv_bfloat162 h0, h1, l0, l1;
    h0.x = __float2bfloat16(v.x);
    h0.y = __float2bfloat16(v.y);
    h1.x = __float2bfloat16(v.z);
    h1.y = __float2bfloat16(v.w);
    l0.x = __float2bfloat16(v.x - __bfloat162float(h0.x));
    l0.y = __float2bfloat16(v.y - __bfloat162float(h0.y));
    l1.x = __float2bfloat16(v.z - __bfloat162float(h1.x));
    l1.y = __float2bfloat16(v.w - __bfloat162float(h1.y));
    *(__nv_bfloat162*)(ph)     = h0;
    *(__nv_bfloat162*)(ph + 2) = h1;
    *(__nv_bfloat162*)(pl)     = l0;
    *(__nv_bfloat162*)(pl + 2) = l1;
}

// ---------------------------------------------------------------------------
// Split-bf16 GEMM tile: out[128 x 128] = X[128,128] @ W^T, W row-major [f][e].
// 8 warps, warp grid 2(m) x 4(n): 64x32 per warp = 4 mtiles x 4 ntiles.
// Smem: bf16 tiles, row stride 136 elements (conflict-free fragment LDS).
// ---------------------------------------------------------------------------
#define XS 136
#define TILE_ELEMS (128 * XS)                 // 17408
#define GEMM_SMEM (4 * TILE_ELEMS * 2)        // 139264 B

__device__ __forceinline__ void gemm_tile_mma(const float* __restrict__ X,
                                              const float* __restrict__ W,
                                              float* __restrict__ out,
                                              int headsplit, int tile,
                                              __nv_bfloat16* sm) {
    __nv_bfloat16* sXh = sm;
    __nv_bfloat16* sXl = sm + TILE_ELEMS;
    __nv_bfloat16* sWh = sm + 2 * TILE_ELEMS;
    __nv_bfloat16* sWl = sm + 3 * TILE_ELEMS;
    const int tid  = threadIdx.x;
    const int row0 = tile * 128;

    // Convert X tile + W to hi/lo bf16 in smem
    {
        const float4* Xv = (const float4*)(X + (size_t)row0 * EMB);
        const float4* Wv = (const float4*)W;
        for (int i = tid; i < 4096; i += 256) {
            const int r  = i >> 5;
            const int c4 = (i & 31) << 2;
            split4(sXh + r * XS + c4, sXl + r * XS + c4, Xv[i]);
            split4(sWh + r * XS + c4, sWl + r * XS + c4, Wv[i]);
        }
    }
    __syncthreads();

    const int lane = tid & 31;
    const int wid  = tid >> 5;
    const int gid  = lane >> 2;
    const int tig  = lane & 3;
    const int wm   = (wid & 1) * 64;   // warp m offset
    const int wn   = (wid >> 1) * 32;  // warp n offset

    float acc[4][4][4];
#pragma unroll
    for (int mt = 0; mt < 4; mt++)
#pragma unroll
        for (int nt = 0; nt < 4; nt++)
#pragma unroll
            for (int j = 0; j < 4; j++) acc[mt][nt][j] = 0.f;

#pragma unroll 1
    for (int ks = 0; ks < 8; ks++) {
        const int k0 = ks * 16 + 2 * tig;
        uint32_t bh[4][2], bl[4][2];
#pragma unroll
        for (int nt = 0; nt < 4; nt++) {
            const int n = wn + nt * 8 + gid;
            const __nv_bfloat16* p = sWh + n * XS + k0;
            const __nv_bfloat16* q = sWl + n * XS + k0;
            bh[nt][0] = *(const uint32_t*)p;
            bh[nt][1] = *(const uint32_t*)(p + 8);
            bl[nt][0] = *(const uint32_t*)q;
            bl[nt][1] = *(const uint32_t*)(q + 8);
        }
#pragma unroll
        for (int mt = 0; mt < 4; mt++) {
            const int r = wm + mt * 16 + gid;
            const __nv_bfloat16* p = sXh + r * XS + k0;
            const __nv_bfloat16* q = sXl + r * XS + k0;
            uint32_t ah[4], al[4];
            ah[0] = *(const uint32_t*)p;
            ah[1] = *(const uint32_t*)(p + 8 * XS);
            ah[2] = *(const uint32_t*)(p + 8);
            ah[3] = *(const uint32_t*)(p + 8 * XS + 8);
            al[0] = *(const uint32_t*)q;
            al[1] = *(const uint32_t*)(q + 8 * XS);
            al[2] = *(const uint32_t*)(q + 8);
            al[3] = *(const uint32_t*)(q + 8 * XS + 8);
#pragma unroll
            for (int nt = 0; nt < 4; nt++) {
                mma16816(acc[mt][nt], ah, bh[nt]);
                mma16816(acc[mt][nt], al, bh[nt]);
                mma16816(acc[mt][nt], ah, bl[nt]);
            }
        }
    }

    // Epilogue: direct global stores (float2 per C-frag half-row)
#pragma unroll
    for (int mt = 0; mt < 4; mt++) {
#pragma unroll
        for (int nt = 0; nt < 4; nt++) {
            const int f = wn + nt * 8 + 2 * tig;
#pragma unroll
            for (int half = 0; half < 2; half++) {
                const int m = row0 + wm + mt * 16 + gid + half * 8;
                float2 v = make_float2(acc[mt][nt][half * 2], acc[mt][nt][half * 2 + 1]);
                if (headsplit) {
                    const int b = m >> 10, c = (m >> 9) & 1, n = m & 511;
                    const int h = f >> 4, dd = f & 15;
                    *(float2*)(out + ((size_t)((b * 16 + h * 2 + c) * NSEQ + n)) * HDIM + dd) = v;
                } else {
                    *(float2*)(out + (size_t)m * EMB + f) = v;
                }
            }
        }
    }
}

// Three projections in one launch: blockIdx.x >> 8 selects Q/K/V
__global__ __launch_bounds__(256) void proj3_mma(const float* __restrict__ Q,
                                                 const float* __restrict__ K,
                                                 const float* __restrict__ V,
                                                 const float* __restrict__ Wq,
                                                 const float* __restrict__ Wk,
                                                 const float* __restrict__ Wv,
                                                 float* __restrict__ qs,
                                                 float* __restrict__ ks,
                                                 float* __restrict__ vs) {
    extern __shared__ __align__(16) __nv_bfloat16 smem[];
    const int which = blockIdx.x >> 8;
    const int tile  = blockIdx.x & 255;
    const float* X = (which == 0) ? Q : (which == 1) ? K : V;
    const float* W = (which == 0) ? Wq : (which == 1) ? Wk : Wv;
    float* O       = (which == 0) ? qs : (which == 1) ? ks : vs;
    gemm_tile_mma(X, W, O, 1, tile, smem);
}

__global__ __launch_bounds__(256) void outproj_mma(const float* __restrict__ X,
                                                   const float* __restrict__ W,
                                                   float* __restrict__ out) {
    extern __shared__ __align__(16) __nv_bfloat16 smem[];
    gemm_tile_mma(X, W, out, 0, blockIdx.x, smem);
}

// ---------------------------------------------------------------------------
// Attention (fp32, verbatim known-good R1): one (b,h,c) batch per block.
// p = exp(L-10) = exp(-20/(exp(dot/2)+1)) exactly; fixed max 10.
// ---------------------------------------------------------------------------
__global__ __launch_bounds__(256) void attn(const float* __restrict__ mask) {
    extern __shared__ float sm[];
    float* ksm = sm;
    float* vsm = sm + 8192;
    float* msm = sm + 16384;
    const int g   = blockIdx.x;
    const int tid = threadIdx.x;
    const int b = g >> 4, h = (g >> 1) & 7, c = g & 1;

    {
        const float4* kg = (const float4*)(g_ks + (size_t)g * (NSEQ * HDIM));
        const float4* vg = (const float4*)(g_vs + (size_t)g * (NSEQ * HDIM));
        float4* ksv = (float4*)ksm;
        float4* vsv = (float4*)vsm;
        for (int idx = tid; idx < 2048; idx += 256) {
            ksv[idx] = kg[idx];
            vsv[idx] = vg[idx];
        }
        const unsigned* mrow = (const unsigned*)mask + (b * 2 + c) * NSEQ;
        for (int idx = tid; idx < NSEQ; idx += 256)
            msm[idx] = (mrow[idx] != 0u) ? 0.f : 1.f;
    }
    __syncthreads();

    float q0[16], q1[16], a0[16], a1[16];
    {
        const float* qg = g_qs + (size_t)g * (NSEQ * HDIM);
#pragma unroll
        for (int d4 = 0; d4 < 4; d4++) {
            *(float4*)(q0 + 4 * d4) = *(const float4*)(qg + (size_t)tid * HDIM + 4 * d4);
            *(float4*)(q1 + 4 * d4) = *(const float4*)(qg + (size_t)(tid + 256) * HDIM + 4 * d4);
        }
#pragma unroll
        for (int d = 0; d < 16; d++) { a0[d] = 0.f; a1[d] = 0.f; }
    }
    float l0 = 0.f, l1 = 0.f;

    for (int j = 0; j < NSEQ; j++) {
        float kj[16], vj[16];
#pragma unroll
        for (int d4 = 0; d4 < 4; d4++) {
            *(float4*)(kj + 4 * d4) = *(const float4*)(ksm + j * HDIM + 4 * d4);
            *(float4*)(vj + 4 * d4) = *(const float4*)(vsm + j * HDIM + 4 * d4);
        }
        float s0a = 0.f, s0b = 0.f, s1a = 0.f, s1b = 0.f;
#pragma unroll
        for (int d = 0; d < 16; d += 2) {
            s0a += q0[d]     * kj[d];
            s0b += q0[d + 1] * kj[d + 1];
            s1a += q1[d]     * kj[d];
            s1b += q1[d + 1] * kj[d + 1];
        }
        const float s0 = s0a + s0b;
        const float s1 = s1a + s1b;
        const float mj = msm[j];
        float t0 = __expf(s0 * 0.5f);
        float t1 = __expf(s1 * 0.5f);
        float p0 = __expf(__fdividef(-20.f, t0 + 1.f)) * mj;
        float p1 = __expf(__fdividef(-20.f, t1 + 1.f)) * mj;
        l0 += p0;
        l1 += p1;
#pragma unroll
        for (int d = 0; d < 16; d++) {
            a0[d] += p0 * vj[d];
            a1[d] += p1 * vj[d];
        }
    }

    const float inv0 = 1.f / l0;
    const float inv1 = 1.f / l1;
    const int mbase = (b * 2 + c) * NSEQ;
    float* o0 = g_att + (size_t)(mbase + tid) * EMB + h * HDIM;
    float* o1 = g_att + (size_t)(mbase + tid + 256) * EMB + h * HDIM;
#pragma unroll
    for (int d4 = 0; d4 < 4; d4++) {
        *(float4*)(o0 + 4 * d4) = make_float4(a0[4 * d4] * inv0, a0[4 * d4 + 1] * inv0,
                                              a0[4 * d4 + 2] * inv0, a0[4 * d4 + 3] * inv0);
        *(float4*)(o1 + 4 * d4) = make_float4(a1[4 * d4] * inv1, a1[4 * d4 + 1] * inv1,
                                              a1[4 * d4 + 2] * inv1, a1[4 * d4 + 3] * inv1);
    }
}

// ---------------------------------------------------------------------------
extern "C" void kernel_launch(void* const* d_in, const int* in_sizes, int n_in,
                              void* d_out, int out_size) {
    const float* Q    = (const float*)d_in[0];
    const float* K    = (const float*)d_in[1];
    const float* V    = (const float*)d_in[2];
    const float* mask = (const float*)d_in[3];
    const float* Wq   = (const float*)d_in[4];
    const float* Wk   = (const float*)d_in[5];
    const float* Wv   = (const float*)d_in[6];
    const float* Wout = (const float*)d_in[7];
    float* out = (float*)d_out;

    const int ATTN_SMEM = (8192 + 8192 + 512) * 4;
    cudaFuncSetAttribute(proj3_mma,  cudaFuncAttributeMaxDynamicSharedMemorySize, GEMM_SMEM);
    cudaFuncSetAttribute(outproj_mma, cudaFuncAttributeMaxDynamicSharedMemorySize, GEMM_SMEM);
    cudaFuncSetAttribute(attn, cudaFuncAttributeMaxDynamicSharedMemorySize, ATTN_SMEM);

    float *qs, *ks, *vs, *att;
    cudaGetSymbolAddress((void**)&qs,  g_qs);
    cudaGetSymbolAddress((void**)&ks,  g_ks);
    cudaGetSymbolAddress((void**)&vs,  g_vs);
    cudaGetSymbolAddress((void**)&att, g_att);

    proj3_mma<<<768, 256, GEMM_SMEM>>>(Q, K, V, Wq, Wk, Wv, qs, ks, vs);
    attn<<<NBATCH, 256, ATTN_SMEM>>>(mask);
    outproj_mma<<<256, 256, GEMM_SMEM>>>(att, Wout, out);
}

// round 8
// speedup vs baseline: 2.4070x; 1.4084x over previous
#include <cuda_runtime.h>
#include <cuda_bf16.h>
#include <cstdint>

#define NSEQ    512
#define EMB     128
#define HDIM    16
#define NBATCH  512          // B*H*C
#define M_TOTAL 32768        // B*C*N

// Scratch (__device__ globals per allocation rules)
__device__ float g_qs[NBATCH * NSEQ * HDIM];   // [g][n][d]
__device__ float g_ks[NBATCH * NSEQ * HDIM];   // [g][n][d]
__device__ float g_vs[NBATCH * NSEQ * HDIM];   // [g][d][n]  (TRANSPOSED)
__device__ float g_att[(size_t)M_TOTAL * EMB];

// ---------------------------------------------------------------------------
// mma.sync m16n8k16 bf16 (arch-unconditional HMMA)
// A frags (lane=4*gid+tig): a0=(gid,2tig) a1=(gid+8,2tig) a2=(gid,2tig+8) a3=(gid+8,2tig+8)
// B frags: b0=(k=2tig,n=gid) b1=(k=2tig+8,n=gid)
// C frags: c0=(gid,2tig) c1=(gid,2tig+1) c2=(gid+8,2tig) c3=(gid+8,2tig+1)
// ---------------------------------------------------------------------------
__device__ __forceinline__ void mma16816(float* c, const uint32_t* a, const uint32_t* b) {
    asm volatile(
        "mma.sync.aligned.m16n8k16.row.col.f32.bf16.bf16.f32 "
        "{%0,%1,%2,%3}, {%4,%5,%6,%7}, {%8,%9}, {%0,%1,%2,%3};"
        : "+f"(c[0]), "+f"(c[1]), "+f"(c[2]), "+f"(c[3])
        : "r"(a[0]), "r"(a[1]), "r"(a[2]), "r"(a[3]), "r"(b[0]), "r"(b[1]));
}

// Split two floats into packed bf16x2 hi + lo (low 16 bits = first element)
__device__ __forceinline__ void pack_split(float p0, float p1, uint32_t& h, uint32_t& l) {
    asm("cvt.rn.bf16x2.f32 %0, %1, %2;" : "=r"(h) : "f"(p1), "f"(p0));
    float h0 = __uint_as_float(h << 16);
    float h1 = __uint_as_float(h & 0xFFFF0000u);
    float l0 = p0 - h0, l1 = p1 - h1;
    asm("cvt.rn.bf16x2.f32 %0, %1, %2;" : "=r"(l) : "f"(l1), "f"(l0));
}

// Split fp32 -> bf16 hi + lo (4-wide, for GEMM smem conversion)
__device__ __forceinline__ void split4(__nv_bfloat16* ph, __nv_bfloat16* pl, float4 v) {
    uint32_t h01, h23, l01, l23;
    pack_split(v.x, v.y, h01, l01);
    pack_split(v.z, v.w, h23, l23);
    *(uint32_t*)(ph)     = h01;
    *(uint32_t*)(ph + 2) = h23;
    *(uint32_t*)(pl)     = l01;
    *(uint32_t*)(pl + 2) = l23;
}

// ---------------------------------------------------------------------------
// Split-bf16 GEMM tile: out[128 x 128] = X[128,128] @ W^T, W row-major [f][e].
// mode 0: plain [m][f];  mode 1: head-split [g][n][d];  mode 2: V transposed [g][d][n]
// ---------------------------------------------------------------------------
#define XS 136
#define TILE_ELEMS (128 * XS)
#define GEMM_SMEM (4 * TILE_ELEMS * 2)        // 139264 B

__device__ __forceinline__ void gemm_tile_mma(const float* __restrict__ X,
                                              const float* __restrict__ W,
                                              float* __restrict__ out,
                                              int mode, int tile,
                                              __nv_bfloat16* sm) {
    __nv_bfloat16* sXh = sm;
    __nv_bfloat16* sXl = sm + TILE_ELEMS;
    __nv_bfloat16* sWh = sm + 2 * TILE_ELEMS;
    __nv_bfloat16* sWl = sm + 3 * TILE_ELEMS;
    const int tid  = threadIdx.x;
    const int row0 = tile * 128;

    {
        const float4* Xv = (const float4*)(X + (size_t)row0 * EMB);
        const float4* Wv = (const float4*)W;
        for (int i = tid; i < 4096; i += 256) {
            const int r  = i >> 5;
            const int c4 = (i & 31) << 2;
            split4(sXh + r * XS + c4, sXl + r * XS + c4, Xv[i]);
            split4(sWh + r * XS + c4, sWl + r * XS + c4, Wv[i]);
        }
    }
    __syncthreads();

    const int lane = tid & 31;
    const int wid  = tid >> 5;
    const int gid  = lane >> 2;
    const int tig  = lane & 3;
    const int wm   = (wid & 1) * 64;
    const int wn   = (wid >> 1) * 32;

    float acc[4][4][4];
#pragma unroll
    for (int mt = 0; mt < 4; mt++)
#pragma unroll
        for (int nt = 0; nt < 4; nt++)
#pragma unroll
            for (int j = 0; j < 4; j++) acc[mt][nt][j] = 0.f;

#pragma unroll 1
    for (int ks = 0; ks < 8; ks++) {
        const int k0 = ks * 16 + 2 * tig;
        uint32_t bh[4][2], bl[4][2];
#pragma unroll
        for (int nt = 0; nt < 4; nt++) {
            const int n = wn + nt * 8 + gid;
            const __nv_bfloat16* p = sWh + n * XS + k0;
            const __nv_bfloat16* q = sWl + n * XS + k0;
            bh[nt][0] = *(const uint32_t*)p;
            bh[nt][1] = *(const uint32_t*)(p + 8);
            bl[nt][0] = *(const uint32_t*)q;
            bl[nt][1] = *(const uint32_t*)(q + 8);
        }
#pragma unroll
        for (int mt = 0; mt < 4; mt++) {
            const int r = wm + mt * 16 + gid;
            const __nv_bfloat16* p = sXh + r * XS + k0;
            const __nv_bfloat16* q = sXl + r * XS + k0;
            uint32_t ah[4], al[4];
            ah[0] = *(const uint32_t*)p;
            ah[1] = *(const uint32_t*)(p + 8 * XS);
            ah[2] = *(const uint32_t*)(p + 8);
            ah[3] = *(const uint32_t*)(p + 8 * XS + 8);
            al[0] = *(const uint32_t*)q;
            al[1] = *(const uint32_t*)(q + 8 * XS);
            al[2] = *(const uint32_t*)(q + 8);
            al[3] = *(const uint32_t*)(q + 8 * XS + 8);
#pragma unroll
            for (int nt = 0; nt < 4; nt++) {
                mma16816(acc[mt][nt], ah, bh[nt]);
                mma16816(acc[mt][nt], al, bh[nt]);
                mma16816(acc[mt][nt], ah, bl[nt]);
            }
        }
    }

#pragma unroll
    for (int mt = 0; mt < 4; mt++) {
#pragma unroll
        for (int nt = 0; nt < 4; nt++) {
            const int f = wn + nt * 8 + 2 * tig;
#pragma unroll
            for (int half = 0; half < 2; half++) {
                const int m = row0 + wm + mt * 16 + gid + half * 8;
                float2 v = make_float2(acc[mt][nt][half * 2], acc[mt][nt][half * 2 + 1]);
                const int b = m >> 10, c = (m >> 9) & 1, n = m & 511;
                const int h = f >> 4, dd = f & 15;
                const int g = b * 16 + h * 2 + c;
                if (mode == 1) {
                    *(float2*)(out + ((size_t)(g * NSEQ + n)) * HDIM + dd) = v;
                } else if (mode == 2) {
                    out[(size_t)g * 8192 + dd * 512 + n]       = v.x;
                    out[(size_t)g * 8192 + (dd + 1) * 512 + n] = v.y;
                } else {
                    *(float2*)(out + (size_t)m * EMB + f) = v;
                }
            }
        }
    }
}

__global__ __launch_bounds__(256) void proj3_mma(const float* __restrict__ Q,
                                                 const float* __restrict__ K,
                                                 const float* __restrict__ V,
                                                 const float* __restrict__ Wq,
                                                 const float* __restrict__ Wk,
                                                 const float* __restrict__ Wv,
                                                 float* __restrict__ qs,
                                                 float* __restrict__ ks,
                                                 float* __restrict__ vs) {
    extern __shared__ __align__(16) __nv_bfloat16 smem[];
    const int which = blockIdx.x >> 8;
    const int tile  = blockIdx.x & 255;
    const float* X = (which == 0) ? Q : (which == 1) ? K : V;
    const float* W = (which == 0) ? Wq : (which == 1) ? Wk : Wv;
    float* O       = (which == 0) ? qs : (which == 1) ? ks : vs;
    gemm_tile_mma(X, W, O, (which == 2) ? 2 : 1, tile, smem);
}

__global__ __launch_bounds__(256) void outproj_mma(const float* __restrict__ X,
                                                   const float* __restrict__ W,
                                                   float* __restrict__ out) {
    extern __shared__ __align__(16) __nv_bfloat16 smem[];
    gemm_tile_mma(X, W, out, 0, blockIdx.x, smem);
}

// ---------------------------------------------------------------------------
// HMMA attention. One block per (b,h,c). 8 warps x 64 q-rows.
// Streams 16 key-chunks of 32; no rescale (fixed max 10):
//   p = exp(-20/(exp(s/2)+1)) * mask,  out = (P @ V) / Sigma p
// K smem: [key][9 words] packed bf16x2 hi/lo.  V smem: [d][260 words] (transposed).
// ---------------------------------------------------------------------------
#define KW 9
#define VW 260
#define ATTN_WORDS (2 * 512 * KW + 2 * 16 * VW + 512)
#define ATTN_SMEM  (ATTN_WORDS * 4)

__global__ __launch_bounds__(256, 1) void attn_mma(const float* __restrict__ mask) {
    extern __shared__ __align__(16) uint32_t smu[];
    uint32_t* khi = smu;
    uint32_t* klo = smu + 512 * KW;
    uint32_t* vhi = smu + 2 * 512 * KW;
    uint32_t* vlo = smu + 2 * 512 * KW + 16 * VW;
    float*    msm = (float*)(smu + 2 * 512 * KW + 2 * 16 * VW);

    const int g   = blockIdx.x;
    const int tid = threadIdx.x;
    const int b = g >> 4, h = (g >> 1) & 7, c = g & 1;
    const int lane = tid & 31;
    const int wid  = tid >> 5;
    const int gid  = lane >> 2;
    const int tig  = lane & 3;

    // ---- load + convert K (hi/lo packed) ----
    {
        const float* kg = g_ks + (size_t)g * 8192;
        for (int i = tid; i < 4096; i += 256) {
            const int key = i >> 3, dp = i & 7;
            float2 f = *(const float2*)(kg + key * 16 + 2 * dp);
            uint32_t hh, ll;
            pack_split(f.x, f.y, hh, ll);
            khi[key * KW + dp] = hh;
            klo[key * KW + dp] = ll;
        }
        const float* vg = g_vs + (size_t)g * 8192;   // [d][key]
        for (int i = tid; i < 4096; i += 256) {
            const int d = i >> 8, kp = i & 255;
            float2 f = *(const float2*)(vg + d * 512 + 2 * kp);
            uint32_t hh, ll;
            pack_split(f.x, f.y, hh, ll);
            vhi[d * VW + kp] = hh;
            vlo[d * VW + kp] = ll;
        }
        const unsigned* mrow = (const unsigned*)mask + (b * 2 + c) * NSEQ;
        for (int i = tid; i < NSEQ; i += 256)
            msm[i] = (mrow[i] != 0u) ? 0.f : 1.f;
    }

    // ---- Q fragments from global (split hi/lo) ----
    uint32_t qh[4][4], ql[4][4];
    {
        const float* qg = g_qs + (size_t)g * 8192 + (size_t)(wid * 64) * HDIM;
#pragma unroll
        for (int mt = 0; mt < 4; mt++) {
            const float* r0 = qg + (mt * 16 + gid) * HDIM;
            const float* r1 = r0 + 8 * HDIM;
            float2 fa = *(const float2*)(r0 + 2 * tig);
            float2 fb = *(const float2*)(r0 + 2 * tig + 8);
            float2 fc = *(const float2*)(r1 + 2 * tig);
            float2 fd = *(const float2*)(r1 + 2 * tig + 8);
            pack_split(fa.x, fa.y, qh[mt][0], ql[mt][0]);
            pack_split(fc.x, fc.y, qh[mt][1], ql[mt][1]);
            pack_split(fb.x, fb.y, qh[mt][2], ql[mt][2]);
            pack_split(fd.x, fd.y, qh[mt][3], ql[mt][3]);
        }
    }
    __syncthreads();

    float oacc[4][2][4];
    float lacc[4][2];
#pragma unroll
    for (int mt = 0; mt < 4; mt++) {
        lacc[mt][0] = 0.f;
        lacc[mt][1] = 0.f;
#pragma unroll
        for (int dnt = 0; dnt < 2; dnt++)
#pragma unroll
            for (int j = 0; j < 4; j++) oacc[mt][dnt][j] = 0.f;
    }

#pragma unroll 1
    for (int ch = 0; ch < 16; ch++) {
        // ---- scores S = Q K^T (raw dot, split-bf16 3x) ----
        float s[4][4][4];
#pragma unroll
        for (int mt = 0; mt < 4; mt++)
#pragma unroll
            for (int nt = 0; nt < 4; nt++)
#pragma unroll
                for (int j = 0; j < 4; j++) s[mt][nt][j] = 0.f;

#pragma unroll
        for (int nt = 0; nt < 4; nt++) {
            const int key = ch * 32 + nt * 8 + gid;
            uint32_t kh[2], kl[2];
            kh[0] = khi[key * KW + tig];
            kh[1] = khi[key * KW + tig + 4];
            kl[0] = klo[key * KW + tig];
            kl[1] = klo[key * KW + tig + 4];
#pragma unroll
            for (int mt = 0; mt < 4; mt++) {
                mma16816(s[mt][nt], qh[mt], kh);
                mma16816(s[mt][nt], ql[mt], kh);
                mma16816(s[mt][nt], qh[mt], kl);
            }
        }

        // ---- softmax numerator + split to bf16 frags ----
        uint32_t ph[4][4][2], pl[4][4][2];
#pragma unroll
        for (int nt = 0; nt < 4; nt++) {
            const float2 m2 = *(const float2*)(msm + ch * 32 + nt * 8 + 2 * tig);
#pragma unroll
            for (int mt = 0; mt < 4; mt++) {
#pragma unroll
                for (int pi = 0; pi < 2; pi++) {
                    const float s0 = s[mt][nt][pi * 2];
                    const float s1 = s[mt][nt][pi * 2 + 1];
                    float p0 = __expf(__fdividef(-20.f, __expf(0.5f * s0) + 1.f)) * m2.x;
                    float p1 = __expf(__fdividef(-20.f, __expf(0.5f * s1) + 1.f)) * m2.y;
                    lacc[mt][pi] += p0 + p1;
                    pack_split(p0, p1, ph[mt][nt][pi], pl[mt][nt][pi]);
                }
            }
        }

        // ---- PV accumulate (split-bf16 3x) ----
#pragma unroll
        for (int ks = 0; ks < 2; ks++) {
#pragma unroll
            for (int dnt = 0; dnt < 2; dnt++) {
                const int d = dnt * 8 + gid;
                const int base = d * VW + ch * 16 + ks * 8 + tig;
                uint32_t vh[2], vl[2];
                vh[0] = vhi[base];
                vh[1] = vhi[base + 4];
                vl[0] = vlo[base];
                vl[1] = vlo[base + 4];
#pragma unroll
                for (int mt = 0; mt < 4; mt++) {
                    uint32_t ah[4] = {ph[mt][2 * ks][0], ph[mt][2 * ks][1],
                                      ph[mt][2 * ks + 1][0], ph[mt][2 * ks + 1][1]};
                    uint32_t al[4] = {pl[mt][2 * ks][0], pl[mt][2 * ks][1],
                                      pl[mt][2 * ks + 1][0], pl[mt][2 * ks + 1][1]};
                    mma16816(oacc[mt][dnt], ah, vh);
                    mma16816(oacc[mt][dnt], al, vh);
                    mma16816(oacc[mt][dnt], ah, vl);
                }
            }
        }
    }

    // ---- reduce l over tig quad, normalize, store ----
    float inv[4][2];
#pragma unroll
    for (int mt = 0; mt < 4; mt++)
#pragma unroll
        for (int pi = 0; pi < 2; pi++) {
            float l = lacc[mt][pi];
            l += __shfl_xor_sync(0xFFFFFFFFu, l, 1);
            l += __shfl_xor_sync(0xFFFFFFFFu, l, 2);
            inv[mt][pi] = 1.f / l;
        }

    const int mbase = (b * 2 + c) * NSEQ;
#pragma unroll
    for (int mt = 0; mt < 4; mt++) {
        const int row = wid * 64 + mt * 16 + gid;
#pragma unroll
        for (int dnt = 0; dnt < 2; dnt++) {
            const int dcol = h * HDIM + dnt * 8 + 2 * tig;
            float* o0 = g_att + (size_t)(mbase + row) * EMB + dcol;
            float* o1 = g_att + (size_t)(mbase + row + 8) * EMB + dcol;
            *(float2*)o0 = make_float2(oacc[mt][dnt][0] * inv[mt][0],
                                       oacc[mt][dnt][1] * inv[mt][0]);
            *(float2*)o1 = make_float2(oacc[mt][dnt][2] * inv[mt][1],
                                       oacc[mt][dnt][3] * inv[mt][1]);
        }
    }
}

// ---------------------------------------------------------------------------
extern "C" void kernel_launch(void* const* d_in, const int* in_sizes, int n_in,
                              void* d_out, int out_size) {
    const float* Q    = (const float*)d_in[0];
    const float* K    = (const float*)d_in[1];
    const float* V    = (const float*)d_in[2];
    const float* mask = (const float*)d_in[3];
    const float* Wq   = (const float*)d_in[4];
    const float* Wk   = (const float*)d_in[5];
    const float* Wv   = (const float*)d_in[6];
    const float* Wout = (const float*)d_in[7];
    float* out = (float*)d_out;

    cudaFuncSetAttribute(proj3_mma,   cudaFuncAttributeMaxDynamicSharedMemorySize, GEMM_SMEM);
    cudaFuncSetAttribute(outproj_mma, cudaFuncAttributeMaxDynamicSharedMemorySize, GEMM_SMEM);
    cudaFuncSetAttribute(attn_mma,    cudaFuncAttributeMaxDynamicSharedMemorySize, ATTN_SMEM);

    float *qs, *ks, *vs, *att;
    cudaGetSymbolAddress((void**)&qs,  g_qs);
    cudaGetSymbolAddress((void**)&ks,  g_ks);
    cudaGetSymbolAddress((void**)&vs,  g_vs);
    cudaGetSymbolAddress((void**)&att, g_att);

    proj3_mma<<<768, 256, GEMM_SMEM>>>(Q, K, V, Wq, Wk, Wv, qs, ks, vs);
    attn_mma<<<NBATCH, 256, ATTN_SMEM>>>(mask);
    outproj_mma<<<256, 256, GEMM_SMEM>>>(att, Wout, out);
}

// round 9
// speedup vs baseline: 2.7368x; 1.1370x over previous
#include <cuda_runtime.h>
#include <cuda_bf16.h>
#include <cstdint>

#define NSEQ    512
#define EMB     128
#define HDIM    16
#define NBATCH  512          // B*H*C
#define M_TOTAL 32768        // B*C*N

// Scratch (__device__ globals per allocation rules)
__device__ float g_qs[NBATCH * NSEQ * HDIM];   // [g][n][d]
__device__ float g_ks[NBATCH * NSEQ * HDIM];   // [g][n][d]
__device__ float g_vs[NBATCH * NSEQ * HDIM];   // [g][d][n]  (TRANSPOSED)
__device__ float g_att[(size_t)M_TOTAL * EMB];
// Preconverted weights: hi/lo bf16, [which][f*128+e]
__device__ __nv_bfloat16 g_wh[4][EMB * EMB];
__device__ __nv_bfloat16 g_wl[4][EMB * EMB];

// ---------------------------------------------------------------------------
// mma.sync m16n8k16 (arch-unconditional HMMA)
// A frags (lane=4*gid+tig): a0=(gid,2tig) a1=(gid+8,2tig) a2=(gid,2tig+8) a3=(gid+8,2tig+8)
// B frags: b0=(k=2tig,n=gid) b1=(k=2tig+8,n=gid)
// C frags: c0=(gid,2tig) c1=(gid,2tig+1) c2=(gid+8,2tig) c3=(gid+8,2tig+1)
// ---------------------------------------------------------------------------
__device__ __forceinline__ void mma16816(float* c, const uint32_t* a, const uint32_t* b) {
    asm volatile(
        "mma.sync.aligned.m16n8k16.row.col.f32.bf16.bf16.f32 "
        "{%0,%1,%2,%3}, {%4,%5,%6,%7}, {%8,%9}, {%0,%1,%2,%3};"
        : "+f"(c[0]), "+f"(c[1]), "+f"(c[2]), "+f"(c[3])
        : "r"(a[0]), "r"(a[1]), "r"(a[2]), "r"(a[3]), "r"(b[0]), "r"(b[1]));
}
__device__ __forceinline__ void mma16816h(float* c, const uint32_t* a, const uint32_t* b) {
    asm volatile(
        "mma.sync.aligned.m16n8k16.row.col.f32.f16.f16.f32 "
        "{%0,%1,%2,%3}, {%4,%5,%6,%7}, {%8,%9}, {%0,%1,%2,%3};"
        : "+f"(c[0]), "+f"(c[1]), "+f"(c[2]), "+f"(c[3])
        : "r"(a[0]), "r"(a[1]), "r"(a[2]), "r"(a[3]), "r"(b[0]), "r"(b[1]));
}

// Split two floats into packed bf16x2 hi + lo (low 16 bits = first element)
__device__ __forceinline__ void pack_split(float p0, float p1, uint32_t& h, uint32_t& l) {
    asm("cvt.rn.bf16x2.f32 %0, %1, %2;" : "=r"(h) : "f"(p1), "f"(p0));
    float h0 = __uint_as_float(h << 16);
    float h1 = __uint_as_float(h & 0xFFFF0000u);
    float l0 = p0 - h0, l1 = p1 - h1;
    asm("cvt.rn.bf16x2.f32 %0, %1, %2;" : "=r"(l) : "f"(l1), "f"(l0));
}
__device__ __forceinline__ uint32_t pack_f16(float p0, float p1) {
    uint32_t r;
    asm("cvt.rn.f16x2.f32 %0, %1, %2;" : "=r"(r) : "f"(p1), "f"(p0));
    return r;
}
__device__ __forceinline__ void split4(__nv_bfloat16* ph, __nv_bfloat16* pl, float4 v) {
    uint32_t h01, h23, l01, l23;
    pack_split(v.x, v.y, h01, l01);
    pack_split(v.z, v.w, h23, l23);
    *(uint32_t*)(ph)     = h01;
    *(uint32_t*)(ph + 2) = h23;
    *(uint32_t*)(pl)     = l01;
    *(uint32_t*)(pl + 2) = l23;
}

// ---------------------------------------------------------------------------
// One-shot weight conversion: 4 matrices fp32 -> bf16 hi/lo (plain layout)
// ---------------------------------------------------------------------------
__global__ __launch_bounds__(256) void wconv(const float* __restrict__ Wq,
                                             const float* __restrict__ Wk,
                                             const float* __restrict__ Wv,
                                             const float* __restrict__ Wout) {
    const int i     = blockIdx.x * 256 + threadIdx.x;   // 0..16383 (float4 id)
    const int which = i >> 12;
    const int e4    = i & 4095;
    const float* W  = (which == 0) ? Wq : (which == 1) ? Wk : (which == 2) ? Wv : Wout;
    float4 v = ((const float4*)W)[e4];
    split4(g_wh[which] + e4 * 4, g_wl[which] + e4 * 4, v);
}

// ---------------------------------------------------------------------------
// Split-bf16 GEMM tile: out[128 x 128] = X[128,128] @ W^T.
// X hi/lo staged in smem (69.6KB -> 2 CTAs/SM); W frags loaded from
// preconverted global bf16 (L1-resident, shared across CTAs).
// mode 0: plain [m][f];  mode 1: head-split [g][n][d];  mode 2: V transposed [g][d][n]
// ---------------------------------------------------------------------------
#define XS 136
#define TILE_ELEMS (128 * XS)
#define GEMM_SMEM (2 * TILE_ELEMS * 2)        // 69632 B

__device__ __forceinline__ void gemm_tile_mma(const float* __restrict__ X,
                                              const __nv_bfloat16* __restrict__ wh,
                                              const __nv_bfloat16* __restrict__ wl,
                                              float* __restrict__ out,
                                              int mode, int tile,
                                              __nv_bfloat16* sm) {
    __nv_bfloat16* sXh = sm;
    __nv_bfloat16* sXl = sm + TILE_ELEMS;
    const int tid  = threadIdx.x;
    const int row0 = tile * 128;

    {
        const float4* Xv = (const float4*)(X + (size_t)row0 * EMB);
        for (int i = tid; i < 4096; i += 256) {
            const int r  = i >> 5;
            const int c4 = (i & 31) << 2;
            split4(sXh + r * XS + c4, sXl + r * XS + c4, Xv[i]);
        }
    }
    __syncthreads();

    const int lane = tid & 31;
    const int wid  = tid >> 5;
    const int gid  = lane >> 2;
    const int tig  = lane & 3;
    const int wm   = (wid & 1) * 64;
    const int wn   = (wid >> 1) * 32;

    float acc[4][4][4];
#pragma unroll
    for (int mt = 0; mt < 4; mt++)
#pragma unroll
        for (int nt = 0; nt < 4; nt++)
#pragma unroll
            for (int j = 0; j < 4; j++) acc[mt][nt][j] = 0.f;

#pragma unroll 1
    for (int ks = 0; ks < 8; ks++) {
        const int k0 = ks * 16 + 2 * tig;
        uint32_t bh[4][2], bl[4][2];
#pragma unroll
        for (int nt = 0; nt < 4; nt++) {
            const int n = wn + nt * 8 + gid;
            const __nv_bfloat16* p = wh + n * EMB + k0;
            const __nv_bfloat16* q = wl + n * EMB + k0;
            bh[nt][0] = *(const uint32_t*)p;
            bh[nt][1] = *(const uint32_t*)(p + 8);
            bl[nt][0] = *(const uint32_t*)q;
            bl[nt][1] = *(const uint32_t*)(q + 8);
        }
#pragma unroll
        for (int mt = 0; mt < 4; mt++) {
            const int r = wm + mt * 16 + gid;
            const __nv_bfloat16* p = sXh + r * XS + k0;
            const __nv_bfloat16* q = sXl + r * XS + k0;
            uint32_t ah[4], al[4];
            ah[0] = *(const uint32_t*)p;
            ah[1] = *(const uint32_t*)(p + 8 * XS);
            ah[2] = *(const uint32_t*)(p + 8);
            ah[3] = *(const uint32_t*)(p + 8 * XS + 8);
            al[0] = *(const uint32_t*)q;
            al[1] = *(const uint32_t*)(q + 8 * XS);
            al[2] = *(const uint32_t*)(q + 8);
            al[3] = *(const uint32_t*)(q + 8 * XS + 8);
#pragma unroll
            for (int nt = 0; nt < 4; nt++) {
                mma16816(acc[mt][nt], ah, bh[nt]);
                mma16816(acc[mt][nt], al, bh[nt]);
                mma16816(acc[mt][nt], ah, bl[nt]);
            }
        }
    }

#pragma unroll
    for (int mt = 0; mt < 4; mt++) {
#pragma unroll
        for (int nt = 0; nt < 4; nt++) {
            const int f = wn + nt * 8 + 2 * tig;
#pragma unroll
            for (int half = 0; half < 2; half++) {
                const int m = row0 + wm + mt * 16 + gid + half * 8;
                float2 v = make_float2(acc[mt][nt][half * 2], acc[mt][nt][half * 2 + 1]);
                const int b = m >> 10, c = (m >> 9) & 1, n = m & 511;
                const int h = f >> 4, dd = f & 15;
                const int g = b * 16 + h * 2 + c;
                if (mode == 1) {
                    *(float2*)(out + ((size_t)(g * NSEQ + n)) * HDIM + dd) = v;
                } else if (mode == 2) {
                    out[(size_t)g * 8192 + dd * 512 + n]       = v.x;
                    out[(size_t)g * 8192 + (dd + 1) * 512 + n] = v.y;
                } else {
                    *(float2*)(out + (size_t)m * EMB + f) = v;
                }
            }
        }
    }
}

__global__ __launch_bounds__(256) void proj3_mma(const float* __restrict__ Q,
                                                 const float* __restrict__ K,
                                                 const float* __restrict__ V,
                                                 float* __restrict__ qs,
                                                 float* __restrict__ ks,
                                                 float* __restrict__ vs) {
    extern __shared__ __align__(16) __nv_bfloat16 smem[];
    const int which = blockIdx.x >> 8;
    const int tile  = blockIdx.x & 255;
    const float* X = (which == 0) ? Q : (which == 1) ? K : V;
    float* O       = (which == 0) ? qs : (which == 1) ? ks : vs;
    gemm_tile_mma(X, g_wh[which], g_wl[which], O, (which == 2) ? 2 : 1, tile, smem);
}

__global__ __launch_bounds__(256) void outproj_mma(const float* __restrict__ X,
                                                   float* __restrict__ out) {
    extern __shared__ __align__(16) __nv_bfloat16 smem[];
    gemm_tile_mma(X, g_wh[3], g_wl[3], out, 0, blockIdx.x, smem);
}

// ---------------------------------------------------------------------------
// HMMA attention. One block per (b,h,c). 8 warps x 64 q-rows.
// QK: split-bf16 3-mma (accurate scores). Softmax: p = exp(-20/(e^{s/2}+1))*m.
// PV: single fp16 mma (P,V quantize to 2^-12 — no split needed).
// K smem: [key][9w] bf16x2 hi/lo.  V smem: fp16x2 [d][260w] (transposed).
// ---------------------------------------------------------------------------
#define KW 9
#define VW 260
#define ATTN_WORDS (2 * 512 * KW + 16 * VW + 512)
#define ATTN_SMEM  (ATTN_WORDS * 4)

__global__ __launch_bounds__(256) void attn_mma(const float* __restrict__ mask) {
    extern __shared__ __align__(16) uint32_t smu[];
    uint32_t* khi = smu;
    uint32_t* klo = smu + 512 * KW;
    uint32_t* vsm = smu + 2 * 512 * KW;
    float*    msm = (float*)(smu + 2 * 512 * KW + 16 * VW);

    const int g   = blockIdx.x;
    const int tid = threadIdx.x;
    const int b = g >> 4, h = (g >> 1) & 7, c = g & 1;
    const int lane = tid & 31;
    const int wid  = tid >> 5;
    const int gid  = lane >> 2;
    const int tig  = lane & 3;

    {
        const float* kg = g_ks + (size_t)g * 8192;
        for (int i = tid; i < 4096; i += 256) {
            const int key = i >> 3, dp = i & 7;
            float2 f = *(const float2*)(kg + key * 16 + 2 * dp);
            uint32_t hh, ll;
            pack_split(f.x, f.y, hh, ll);
            khi[key * KW + dp] = hh;
            klo[key * KW + dp] = ll;
        }
        const float* vg = g_vs + (size_t)g * 8192;   // [d][key]
        for (int i = tid; i < 4096; i += 256) {
            const int d = i >> 8, kp = i & 255;
            float2 f = *(const float2*)(vg + d * 512 + 2 * kp);
            vsm[d * VW + kp] = pack_f16(f.x, f.y);
        }
        const unsigned* mrow = (const unsigned*)mask + (b * 2 + c) * NSEQ;
        for (int i = tid; i < NSEQ; i += 256)
            msm[i] = (mrow[i] != 0u) ? 0.f : 1.f;
    }

    // Q fragments (split hi/lo bf16)
    uint32_t qh[4][4], ql[4][4];
    {
        const float* qg = g_qs + (size_t)g * 8192 + (size_t)(wid * 64) * HDIM;
#pragma unroll
        for (int mt = 0; mt < 4; mt++) {
            const float* r0 = qg + (mt * 16 + gid) * HDIM;
            const float* r1 = r0 + 8 * HDIM;
            float2 fa = *(const float2*)(r0 + 2 * tig);
            float2 fb = *(const float2*)(r0 + 2 * tig + 8);
            float2 fc = *(const float2*)(r1 + 2 * tig);
            float2 fd = *(const float2*)(r1 + 2 * tig + 8);
            pack_split(fa.x, fa.y, qh[mt][0], ql[mt][0]);
            pack_split(fc.x, fc.y, qh[mt][1], ql[mt][1]);
            pack_split(fb.x, fb.y, qh[mt][2], ql[mt][2]);
            pack_split(fd.x, fd.y, qh[mt][3], ql[mt][3]);
        }
    }
    __syncthreads();

    float oacc[4][2][4];
    float lacc[4][2];
#pragma unroll
    for (int mt = 0; mt < 4; mt++) {
        lacc[mt][0] = 0.f;
        lacc[mt][1] = 0.f;
#pragma unroll
        for (int dnt = 0; dnt < 2; dnt++)
#pragma unroll
            for (int j = 0; j < 4; j++) oacc[mt][dnt][j] = 0.f;
    }

#pragma unroll 1
    for (int ch = 0; ch < 16; ch++) {
        // scores S = Q K^T (split-bf16 3x)
        float s[4][4][4];
#pragma unroll
        for (int mt = 0; mt < 4; mt++)
#pragma unroll
            for (int nt = 0; nt < 4; nt++)
#pragma unroll
                for (int j = 0; j < 4; j++) s[mt][nt][j] = 0.f;

#pragma unroll
        for (int nt = 0; nt < 4; nt++) {
            const int key = ch * 32 + nt * 8 + gid;
            uint32_t kh[2], kl[2];
            kh[0] = khi[key * KW + tig];
            kh[1] = khi[key * KW + tig + 4];
            kl[0] = klo[key * KW + tig];
            kl[1] = klo[key * KW + tig + 4];
#pragma unroll
            for (int mt = 0; mt < 4; mt++) {
                mma16816(s[mt][nt], qh[mt], kh);
                mma16816(s[mt][nt], ql[mt], kh);
                mma16816(s[mt][nt], qh[mt], kl);
            }
        }

        // softmax numerator -> fp16 P frags
        uint32_t pf[4][4][2];
#pragma unroll
        for (int nt = 0; nt < 4; nt++) {
            const float2 m2 = *(const float2*)(msm + ch * 32 + nt * 8 + 2 * tig);
#pragma unroll
            for (int mt = 0; mt < 4; mt++) {
#pragma unroll
                for (int pi = 0; pi < 2; pi++) {
                    const float s0 = s[mt][nt][pi * 2];
                    const float s1 = s[mt][nt][pi * 2 + 1];
                    float p0 = __expf(__fdividef(-20.f, __expf(0.5f * s0) + 1.f)) * m2.x;
                    float p1 = __expf(__fdividef(-20.f, __expf(0.5f * s1) + 1.f)) * m2.y;
                    lacc[mt][pi] += p0 + p1;
                    pf[mt][nt][pi] = pack_f16(p0, p1);
                }
            }
        }

        // PV accumulate (single fp16 mma)
#pragma unroll
        for (int ks = 0; ks < 2; ks++) {
#pragma unroll
            for (int dnt = 0; dnt < 2; dnt++) {
                const int d = dnt * 8 + gid;
                const int base = d * VW + ch * 16 + ks * 8 + tig;
                uint32_t vh[2];
                vh[0] = vsm[base];
                vh[1] = vsm[base + 4];
#pragma unroll
                for (int mt = 0; mt < 4; mt++) {
                    uint32_t ap[4] = {pf[mt][2 * ks][0], pf[mt][2 * ks][1],
                                      pf[mt][2 * ks + 1][0], pf[mt][2 * ks + 1][1]};
                    mma16816h(oacc[mt][dnt], ap, vh);
                }
            }
        }
    }

    float inv[4][2];
#pragma unroll
    for (int mt = 0; mt < 4; mt++)
#pragma unroll
        for (int pi = 0; pi < 2; pi++) {
            float l = lacc[mt][pi];
            l += __shfl_xor_sync(0xFFFFFFFFu, l, 1);
            l += __shfl_xor_sync(0xFFFFFFFFu, l, 2);
            inv[mt][pi] = 1.f / l;
        }

    const int mbase = (b * 2 + c) * NSEQ;
#pragma unroll
    for (int mt = 0; mt < 4; mt++) {
        const int row = wid * 64 + mt * 16 + gid;
#pragma unroll
        for (int dnt = 0; dnt < 2; dnt++) {
            const int dcol = h * HDIM + dnt * 8 + 2 * tig;
            float* o0 = g_att + (size_t)(mbase + row) * EMB + dcol;
            float* o1 = g_att + (size_t)(mbase + row + 8) * EMB + dcol;
            *(float2*)o0 = make_float2(oacc[mt][dnt][0] * inv[mt][0],
                                       oacc[mt][dnt][1] * inv[mt][0]);
            *(float2*)o1 = make_float2(oacc[mt][dnt][2] * inv[mt][1],
                                       oacc[mt][dnt][3] * inv[mt][1]);
        }
    }
}

// ---------------------------------------------------------------------------
extern "C" void kernel_launch(void* const* d_in, const int* in_sizes, int n_in,
                              void* d_out, int out_size) {
    const float* Q    = (const float*)d_in[0];
    const float* K    = (const float*)d_in[1];
    const float* V    = (const float*)d_in[2];
    const float* mask = (const float*)d_in[3];
    const float* Wq   = (const float*)d_in[4];
    const float* Wk   = (const float*)d_in[5];
    const float* Wv   = (const float*)d_in[6];
    const float* Wout = (const float*)d_in[7];
    float* out = (float*)d_out;

    cudaFuncSetAttribute(proj3_mma,   cudaFuncAttributeMaxDynamicSharedMemorySize, GEMM_SMEM);
    cudaFuncSetAttribute(outproj_mma, cudaFuncAttributeMaxDynamicSharedMemorySize, GEMM_SMEM);
    cudaFuncSetAttribute(attn_mma,    cudaFuncAttributeMaxDynamicSharedMemorySize, ATTN_SMEM);

    float *qs, *ks, *vs, *att;
    cudaGetSymbolAddress((void**)&qs,  g_qs);
    cudaGetSymbolAddress((void**)&ks,  g_ks);
    cudaGetSymbolAddress((void**)&vs,  g_vs);
    cudaGetSymbolAddress((void**)&att, g_att);

    wconv<<<64, 256>>>(Wq, Wk, Wv, Wout);
    proj3_mma<<<768, 256, GEMM_SMEM>>>(Q, K, V, qs, ks, vs);
    attn_mma<<<NBATCH, 256, ATTN_SMEM>>>(mask);
    outproj_mma<<<256, 256, GEMM_SMEM>>>(att, out);
}

// round 10
// speedup vs baseline: 3.6764x; 1.3433x over previous
#include <cuda_runtime.h>
#include <cuda_bf16.h>
#include <cuda_fp16.h>
#include <cstdint>

#define NSEQ    512
#define EMB     128
#define HDIM    16
#define NBATCH  512          // B*H*C
#define M_TOTAL 32768        // B*C*N

// Scratch (__device__ globals per allocation rules)
// Q,K packed bf16 hi/lo: [g][n][w0..7 = hi pairs, w8..15 = lo pairs]
__device__ uint32_t g_qp[NBATCH * NSEQ * 16];
__device__ uint32_t g_kp[NBATCH * NSEQ * 16];
// V fp16 transposed: [g][d][n]
__device__ __half   g_vp[NBATCH * HDIM * NSEQ];
__device__ float    g_att[(size_t)M_TOTAL * EMB];
// Preconverted weights: hi/lo bf16, [which][f*128+e]
__device__ __nv_bfloat16 g_wh[4][EMB * EMB];
__device__ __nv_bfloat16 g_wl[4][EMB * EMB];

// ---------------------------------------------------------------------------
// mma.sync m16n8k16 (arch-unconditional HMMA)
// ---------------------------------------------------------------------------
__device__ __forceinline__ void mma16816(float* c, const uint32_t* a, const uint32_t* b) {
    asm volatile(
        "mma.sync.aligned.m16n8k16.row.col.f32.bf16.bf16.f32 "
        "{%0,%1,%2,%3}, {%4,%5,%6,%7}, {%8,%9}, {%0,%1,%2,%3};"
        : "+f"(c[0]), "+f"(c[1]), "+f"(c[2]), "+f"(c[3])
        : "r"(a[0]), "r"(a[1]), "r"(a[2]), "r"(a[3]), "r"(b[0]), "r"(b[1]));
}
__device__ __forceinline__ void mma16816h(float* c, const uint32_t* a, const uint32_t* b) {
    asm volatile(
        "mma.sync.aligned.m16n8k16.row.col.f32.f16.f16.f32 "
        "{%0,%1,%2,%3}, {%4,%5,%6,%7}, {%8,%9}, {%0,%1,%2,%3};"
        : "+f"(c[0]), "+f"(c[1]), "+f"(c[2]), "+f"(c[3])
        : "r"(a[0]), "r"(a[1]), "r"(a[2]), "r"(a[3]), "r"(b[0]), "r"(b[1]));
}

// Split two floats into packed bf16x2 hi + lo (low 16 bits = first element)
__device__ __forceinline__ void pack_split(float p0, float p1, uint32_t& h, uint32_t& l) {
    asm("cvt.rn.bf16x2.f32 %0, %1, %2;" : "=r"(h) : "f"(p1), "f"(p0));
    float h0 = __uint_as_float(h << 16);
    float h1 = __uint_as_float(h & 0xFFFF0000u);
    float l0 = p0 - h0, l1 = p1 - h1;
    asm("cvt.rn.bf16x2.f32 %0, %1, %2;" : "=r"(l) : "f"(l1), "f"(l0));
}
__device__ __forceinline__ uint32_t pack_f16(float p0, float p1) {
    uint32_t r;
    asm("cvt.rn.f16x2.f32 %0, %1, %2;" : "=r"(r) : "f"(p1), "f"(p0));
    return r;
}
__device__ __forceinline__ void split4(__nv_bfloat16* ph, __nv_bfloat16* pl, float4 v) {
    uint32_t h01, h23, l01, l23;
    pack_split(v.x, v.y, h01, l01);
    pack_split(v.z, v.w, h23, l23);
    *(uint32_t*)(ph)     = h01;
    *(uint32_t*)(ph + 2) = h23;
    *(uint32_t*)(pl)     = l01;
    *(uint32_t*)(pl + 2) = l23;
}

// ---------------------------------------------------------------------------
// One-shot weight conversion
// ---------------------------------------------------------------------------
__global__ __launch_bounds__(256) void wconv(const float* __restrict__ Wq,
                                             const float* __restrict__ Wk,
                                             const float* __restrict__ Wv,
                                             const float* __restrict__ Wout) {
    const int i     = blockIdx.x * 256 + threadIdx.x;
    const int which = i >> 12;
    const int e4    = i & 4095;
    const float* W  = (which == 0) ? Wq : (which == 1) ? Wk : (which == 2) ? Wv : Wout;
    float4 v = ((const float4*)W)[e4];
    split4(g_wh[which] + e4 * 4, g_wl[which] + e4 * 4, v);
}

// ---------------------------------------------------------------------------
// Split-bf16 GEMM tile: out[128 x 128] = X[128,128] @ W^T.
// X hi/lo in smem; W frags from preconverted global bf16 (L1 resident).
// mode 0: fp32 [m][f]; mode 1: packed bf16 hi/lo [g][n][16w]; mode 2: fp16 [g][d][n]
// ---------------------------------------------------------------------------
#define XS 136
#define TILE_ELEMS (128 * XS)
#define GEMM_SMEM (2 * TILE_ELEMS * 2)        // 69632 B

__device__ __forceinline__ void gemm_tile_mma(const float* __restrict__ X,
                                              const __nv_bfloat16* __restrict__ wh,
                                              const __nv_bfloat16* __restrict__ wl,
                                              void* __restrict__ outv,
                                              int mode, int tile,
                                              __nv_bfloat16* sm) {
    __nv_bfloat16* sXh = sm;
    __nv_bfloat16* sXl = sm + TILE_ELEMS;
    const int tid  = threadIdx.x;
    const int row0 = tile * 128;

    {
        const float4* Xv = (const float4*)(X + (size_t)row0 * EMB);
        for (int i = tid; i < 4096; i += 256) {
            const int r  = i >> 5;
            const int c4 = (i & 31) << 2;
            split4(sXh + r * XS + c4, sXl + r * XS + c4, Xv[i]);
        }
    }
    __syncthreads();

    const int lane = tid & 31;
    const int wid  = tid >> 5;
    const int gid  = lane >> 2;
    const int tig  = lane & 3;
    const int wm   = (wid & 1) * 64;
    const int wn   = (wid >> 1) * 32;

    float acc[4][4][4];
#pragma unroll
    for (int mt = 0; mt < 4; mt++)
#pragma unroll
        for (int nt = 0; nt < 4; nt++)
#pragma unroll
            for (int j = 0; j < 4; j++) acc[mt][nt][j] = 0.f;

#pragma unroll 1
    for (int ks = 0; ks < 8; ks++) {
        const int k0 = ks * 16 + 2 * tig;
        uint32_t bh[4][2], bl[4][2];
#pragma unroll
        for (int nt = 0; nt < 4; nt++) {
            const int n = wn + nt * 8 + gid;
            const __nv_bfloat16* p = wh + n * EMB + k0;
            const __nv_bfloat16* q = wl + n * EMB + k0;
            bh[nt][0] = *(const uint32_t*)p;
            bh[nt][1] = *(const uint32_t*)(p + 8);
            bl[nt][0] = *(const uint32_t*)q;
            bl[nt][1] = *(const uint32_t*)(q + 8);
        }
#pragma unroll
        for (int mt = 0; mt < 4; mt++) {
            const int r = wm + mt * 16 + gid;
            const __nv_bfloat16* p = sXh + r * XS + k0;
            const __nv_bfloat16* q = sXl + r * XS + k0;
            uint32_t ah[4], al[4];
            ah[0] = *(const uint32_t*)p;
            ah[1] = *(const uint32_t*)(p + 8 * XS);
            ah[2] = *(const uint32_t*)(p + 8);
            ah[3] = *(const uint32_t*)(p + 8 * XS + 8);
            al[0] = *(const uint32_t*)q;
            al[1] = *(const uint32_t*)(q + 8 * XS);
            al[2] = *(const uint32_t*)(q + 8);
            al[3] = *(const uint32_t*)(q + 8 * XS + 8);
#pragma unroll
            for (int nt = 0; nt < 4; nt++) {
                mma16816(acc[mt][nt], ah, bh[nt]);
                mma16816(acc[mt][nt], al, bh[nt]);
                mma16816(acc[mt][nt], ah, bl[nt]);
            }
        }
    }

#pragma unroll
    for (int mt = 0; mt < 4; mt++) {
#pragma unroll
        for (int nt = 0; nt < 4; nt++) {
            const int f = wn + nt * 8 + 2 * tig;
#pragma unroll
            for (int half = 0; half < 2; half++) {
                const int m = row0 + wm + mt * 16 + gid + half * 8;
                float2 v = make_float2(acc[mt][nt][half * 2], acc[mt][nt][half * 2 + 1]);
                const int b = m >> 10, c = (m >> 9) & 1, n = m & 511;
                const int h = f >> 4, dd = f & 15;
                const int g = b * 16 + h * 2 + c;
                if (mode == 1) {
                    // packed bf16 hi/lo, word (dd>>1), row [g][n]
                    uint32_t hh, ll;
                    pack_split(v.x, v.y, hh, ll);
                    uint32_t* row = (uint32_t*)outv + ((size_t)(g * NSEQ + n)) * 16;
                    row[dd >> 1]       = hh;
                    row[8 + (dd >> 1)] = ll;
                } else if (mode == 2) {
                    __half* vp = (__half*)outv + (size_t)g * 8192;
                    vp[dd * 512 + n]       = __float2half_rn(v.x);
                    vp[(dd + 1) * 512 + n] = __float2half_rn(v.y);
                } else {
                    *(float2*)((float*)outv + (size_t)m * EMB + f) = v;
                }
            }
        }
    }
}

__global__ __launch_bounds__(256) void proj3_mma(const float* __restrict__ Q,
                                                 const float* __restrict__ K,
                                                 const float* __restrict__ V) {
    extern __shared__ __align__(16) __nv_bfloat16 smem[];
    const int which = blockIdx.x >> 8;
    const int tile  = blockIdx.x & 255;
    const float* X = (which == 0) ? Q : (which == 1) ? K : V;
    void* O        = (which == 0) ? (void*)g_qp : (which == 1) ? (void*)g_kp : (void*)g_vp;
    gemm_tile_mma(X, g_wh[which], g_wl[which], O, (which == 2) ? 2 : 1, tile, smem);
}

__global__ __launch_bounds__(256) void outproj_mma(const float* __restrict__ X,
                                                   float* __restrict__ out) {
    extern __shared__ __align__(16) __nv_bfloat16 smem[];
    gemm_tile_mma(X, g_wh[3], g_wl[3], out, 0, blockIdx.x, smem);
}

// ---------------------------------------------------------------------------
// HMMA attention. grid = 1024: block = (g, qhalf); 8 warps x 32 q-rows = 256 rows.
// QK: split-bf16 3-mma. Softmax: p = exp2(C * rcp(exp2(c1*s)+1)) * mask.
// PV: single fp16 mma. All K/V/Q conversions precomputed by proj3.
// ---------------------------------------------------------------------------
#define KW 9
#define VW 260
#define ATTN_WORDS (2 * 512 * KW + 16 * VW + 512)
#define ATTN_SMEM  (ATTN_WORDS * 4)

__global__ __launch_bounds__(256) void attn_mma(const float* __restrict__ mask) {
    extern __shared__ __align__(16) uint32_t smu[];
    uint32_t* khi = smu;
    uint32_t* klo = smu + 512 * KW;
    uint32_t* vsm = smu + 2 * 512 * KW;
    float*    msm = (float*)(smu + 2 * 512 * KW + 16 * VW);

    const int g    = blockIdx.x >> 1;
    const int qhx  = blockIdx.x & 1;
    const int tid  = threadIdx.x;
    const int b = g >> 4, h = (g >> 1) & 7, c = g & 1;
    const int lane = tid & 31;
    const int wid  = tid >> 5;
    const int gid  = lane >> 2;
    const int tig  = lane & 3;

    // ---- copy precomputed K (packed hi/lo) into smem ----
    {
        const uint4* kg = (const uint4*)(g_kp + (size_t)g * 8192);
        for (int i = tid; i < 2048; i += 256) {
            uint4 w = kg[i];
            const int key = i >> 2, seg = i & 3;
            uint32_t* dst = (seg < 2) ? (khi + key * KW + 4 * seg)
                                      : (klo + key * KW + 4 * (seg - 2));
            dst[0] = w.x; dst[1] = w.y; dst[2] = w.z; dst[3] = w.w;
        }
        const uint4* vg = (const uint4*)(g_vp + (size_t)g * 8192);
        for (int i = tid; i < 1024; i += 256) {
            uint4 w = vg[i];
            const int d = i >> 6, j4 = (i & 63) * 4;
            uint32_t* dst = vsm + d * VW + j4;
            dst[0] = w.x; dst[1] = w.y; dst[2] = w.z; dst[3] = w.w;
        }
        const unsigned* mrow = (const unsigned*)mask + (b * 2 + c) * NSEQ;
        for (int i = tid; i < NSEQ; i += 256)
            msm[i] = (mrow[i] != 0u) ? 0.f : 1.f;
    }

    // ---- Q fragments direct from packed global ----
    uint32_t qh[2][4], ql[2][4];
    {
        const uint32_t* qg = g_qp + (size_t)g * 8192 + (size_t)(qhx * 256 + wid * 32) * 16;
#pragma unroll
        for (int mt = 0; mt < 2; mt++) {
            const uint32_t* r0 = qg + (mt * 16 + gid) * 16;
            const uint32_t* r1 = r0 + 128;
            qh[mt][0] = r0[tig];      ql[mt][0] = r0[8 + tig];
            qh[mt][1] = r1[tig];      ql[mt][1] = r1[8 + tig];
            qh[mt][2] = r0[tig + 4];  ql[mt][2] = r0[12 + tig];
            qh[mt][3] = r1[tig + 4];  ql[mt][3] = r1[12 + tig];
        }
    }
    __syncthreads();

    float oacc[2][2][4];
    float lacc[2][2];
#pragma unroll
    for (int mt = 0; mt < 2; mt++) {
        lacc[mt][0] = 0.f;
        lacc[mt][1] = 0.f;
#pragma unroll
        for (int dnt = 0; dnt < 2; dnt++)
#pragma unroll
            for (int j = 0; j < 4; j++) oacc[mt][dnt][j] = 0.f;
    }

    const float C1 = 0.72134752044f;    // 0.5*log2(e)
    const float C2 = -28.8539008178f;   // -20*log2(e)

#pragma unroll 1
    for (int ch = 0; ch < 16; ch++) {
        float s[2][4][4];
#pragma unroll
        for (int mt = 0; mt < 2; mt++)
#pragma unroll
            for (int nt = 0; nt < 4; nt++)
#pragma unroll
                for (int j = 0; j < 4; j++) s[mt][nt][j] = 0.f;

#pragma unroll
        for (int nt = 0; nt < 4; nt++) {
            const int key = ch * 32 + nt * 8 + gid;
            uint32_t kh[2], kl[2];
            kh[0] = khi[key * KW + tig];
            kh[1] = khi[key * KW + tig + 4];
            kl[0] = klo[key * KW + tig];
            kl[1] = klo[key * KW + tig + 4];
#pragma unroll
            for (int mt = 0; mt < 2; mt++) {
                mma16816(s[mt][nt], qh[mt], kh);
                mma16816(s[mt][nt], ql[mt], kh);
                mma16816(s[mt][nt], qh[mt], kl);
            }
        }

        // softmax numerator -> fp16 P frags
        uint32_t pf[2][4][2];
#pragma unroll
        for (int nt = 0; nt < 4; nt++) {
            const float2 m2 = *(const float2*)(msm + ch * 32 + nt * 8 + 2 * tig);
#pragma unroll
            for (int mt = 0; mt < 2; mt++) {
#pragma unroll
                for (int pi = 0; pi < 2; pi++) {
                    const float s0 = s[mt][pi ? nt : nt][pi * 2];      // c[2pi], c[2pi+1]
                    const float s1 = s[mt][nt][pi * 2 + 1];
                    float t0, t1, r0, r1, p0, p1;
                    asm("ex2.approx.ftz.f32 %0, %1;" : "=f"(t0) : "f"(s[mt][nt][pi * 2] * C1));
                    asm("ex2.approx.ftz.f32 %0, %1;" : "=f"(t1) : "f"(s1 * C1));
                    asm("rcp.approx.ftz.f32 %0, %1;" : "=f"(r0) : "f"(t0 + 1.f));
                    asm("rcp.approx.ftz.f32 %0, %1;" : "=f"(r1) : "f"(t1 + 1.f));
                    asm("ex2.approx.ftz.f32 %0, %1;" : "=f"(p0) : "f"(r0 * C2));
                    asm("ex2.approx.ftz.f32 %0, %1;" : "=f"(p1) : "f"(r1 * C2));
                    p0 *= m2.x;
                    p1 *= m2.y;
                    lacc[mt][pi] += p0 + p1;
                    pf[mt][nt][pi] = pack_f16(p0, p1);
                    (void)s0;
                }
            }
        }

        // PV accumulate (single fp16 mma)
#pragma unroll
        for (int ks = 0; ks < 2; ks++) {
#pragma unroll
            for (int dnt = 0; dnt < 2; dnt++) {
                const int d = dnt * 8 + gid;
                const int base = d * VW + ch * 16 + ks * 8 + tig;
                uint32_t vh[2];
                vh[0] = vsm[base];
                vh[1] = vsm[base + 4];
#pragma unroll
                for (int mt = 0; mt < 2; mt++) {
                    uint32_t ap[4] = {pf[mt][2 * ks][0], pf[mt][2 * ks][1],
                                      pf[mt][2 * ks + 1][0], pf[mt][2 * ks + 1][1]};
                    mma16816h(oacc[mt][dnt], ap, vh);
                }
            }
        }
    }

    float inv[2][2];
#pragma unroll
    for (int mt = 0; mt < 2; mt++)
#pragma unroll
        for (int pi = 0; pi < 2; pi++) {
            float l = lacc[mt][pi];
            l += __shfl_xor_sync(0xFFFFFFFFu, l, 1);
            l += __shfl_xor_sync(0xFFFFFFFFu, l, 2);
            inv[mt][pi] = 1.f / l;
        }

    const int mbase = (b * 2 + c) * NSEQ;
#pragma unroll
    for (int mt = 0; mt < 2; mt++) {
        const int row = qhx * 256 + wid * 32 + mt * 16 + gid;
#pragma unroll
        for (int dnt = 0; dnt < 2; dnt++) {
            const int dcol = h * HDIM + dnt * 8 + 2 * tig;
            float* o0 = g_att + (size_t)(mbase + row) * EMB + dcol;
            float* o1 = g_att + (size_t)(mbase + row + 8) * EMB + dcol;
            *(float2*)o0 = make_float2(oacc[mt][dnt][0] * inv[mt][0],
                                       oacc[mt][dnt][1] * inv[mt][0]);
            *(float2*)o1 = make_float2(oacc[mt][dnt][2] * inv[mt][1],
                                       oacc[mt][dnt][3] * inv[mt][1]);
        }
    }
}

// ---------------------------------------------------------------------------
extern "C" void kernel_launch(void* const* d_in, const int* in_sizes, int n_in,
                              void* d_out, int out_size) {
    const float* Q    = (const float*)d_in[0];
    const float* K    = (const float*)d_in[1];
    const float* V    = (const float*)d_in[2];
    const float* mask = (const float*)d_in[3];
    const float* Wq   = (const float*)d_in[4];
    const float* Wk   = (const float*)d_in[5];
    const float* Wv   = (const float*)d_in[6];
    const float* Wout = (const float*)d_in[7];
    float* out = (float*)d_out;

    cudaFuncSetAttribute(proj3_mma,   cudaFuncAttributeMaxDynamicSharedMemorySize, GEMM_SMEM);
    cudaFuncSetAttribute(outproj_mma, cudaFuncAttributeMaxDynamicSharedMemorySize, GEMM_SMEM);
    cudaFuncSetAttribute(attn_mma,    cudaFuncAttributeMaxDynamicSharedMemorySize, ATTN_SMEM);

    float* att;
    cudaGetSymbolAddress((void**)&att, g_att);

    wconv<<<64, 256>>>(Wq, Wk, Wv, Wout);
    proj3_mma<<<768, 256, GEMM_SMEM>>>(Q, K, V);
    attn_mma<<<1024, 256, ATTN_SMEM>>>(mask);
    outproj_mma<<<256, 256, GEMM_SMEM>>>(att, out);
}